// round 5
// baseline (speedup 1.0000x reference)
#include <cuda_runtime.h>
#include <cuda_fp16.h>
#include <cuda_bf16.h>

#define NN 50000
#define EE 1600000
#define ETOT (EE + NN)
#define HD 128
#define SCAN_B 1024

typedef unsigned long long ull;

// ---------------- scratch (static device globals; no allocation) ------------
__device__ __half g_xl16[NN * HD];    // fp16 mirror of xl (gathered per edge)
__device__ float  g_xr[NN * HD];
__device__ int    g_cnt[NN];
__device__ int    g_rowptr[NN + 1];
__device__ int    g_cursor[NN];
__device__ int    g_src[ETOT];
__device__ int    g_bsum[64];
__device__ int    g_boff[64];

// ---------------- f32x2 packed-math helpers (sm_103a) ------------------------
__device__ __forceinline__ ull pack2(float lo, float hi) {
    ull r; asm("mov.b64 %0, {%1, %2};" : "=l"(r) : "f"(lo), "f"(hi)); return r;
}
__device__ __forceinline__ float2 unpack2(ull v) {
    float2 r; asm("mov.b64 {%0, %1}, %2;" : "=f"(r.x), "=f"(r.y) : "l"(v)); return r;
}
__device__ __forceinline__ void fma2(ull& d, ull a, ull b) {
    asm("fma.rn.f32x2 %0, %1, %2, %0;" : "+l"(d) : "l"(a), "l"(b));
}
__device__ __forceinline__ ull fma2o(ull a, ull b, ull c) {
    ull d; asm("fma.rn.f32x2 %0, %1, %2, %3;" : "=l"(d) : "l"(a), "l"(b), "l"(c)); return d;
}
__device__ __forceinline__ ull add2o(ull a, ull b) {
    ull d; asm("add.rn.f32x2 %0, %1, %2;" : "=l"(d) : "l"(a), "l"(b)); return d;
}
__device__ __forceinline__ ull mul2o(ull a, ull b) {
    ull d; asm("mul.rn.f32x2 %0, %1, %2;" : "=l"(d) : "l"(a), "l"(b)); return d;
}

// ---------------- small init kernels ----------------------------------------
__global__ void init_out_kernel(float* __restrict__ out, int out_elems) {
    int i = blockIdx.x * blockDim.x + threadIdx.x;
    if (i < out_elems) out[i] = 0.0f;
}
__global__ void init_cnt_kernel(int n) {
    int i = blockIdx.x * blockDim.x + threadIdx.x;
    if (i < n) g_cnt[i] = 1;                 // self-loop pre-count
}

// ---------------- register-tiled dual GEMM ----------------------------------
__global__ void __launch_bounds__(256, 2)
gemm_tiled_kernel(const float* __restrict__ x,
                  const float* __restrict__ Wl, const float* __restrict__ bl,
                  const float* __restrict__ Wr, const float* __restrict__ br,
                  int n) {
    extern __shared__ float sm[];
    float* xs = sm;                 // [64][128]
    float* ws = sm + 64 * HD;       // [128][128]

    const float* W    = blockIdx.y ? Wr : Wl;
    const float* bvec = blockIdx.y ? br : bl;

    int tid  = threadIdx.x;
    int lane = tid & 31;
    int w    = tid >> 5;
    int row0 = blockIdx.x * 64;

    for (int i4 = tid; i4 < 64 * 32; i4 += 256) {
        int r = i4 >> 5;
        int row = row0 + r;
        float4 v = make_float4(0.f, 0.f, 0.f, 0.f);
        if (row < n) v = ((const float4*)x)[row * 32 + (i4 & 31)];
        ((float4*)xs)[i4] = v;
    }
    for (int i4 = tid; i4 < 128 * 32; i4 += 256)
        ((float4*)ws)[i4] = ((const float4*)W)[i4];
    __syncthreads();

    const float* arow = xs + (w * 8) * HD;
    ull accp[8][2];
#pragma unroll
    for (int r = 0; r < 8; r++) { accp[r][0] = 0ull; accp[r][1] = 0ull; }

#pragma unroll 4
    for (int k = 0; k < HD; k += 2) {
        float2 a01[8];
#pragma unroll
        for (int r = 0; r < 8; r++)
            a01[r] = *(const float2*)(arow + r * HD + k);

        float4 b0 = *(const float4*)(ws + k * HD + 4 * lane);
        float4 b1 = *(const float4*)(ws + (k + 1) * HD + 4 * lane);
        ull bp00 = pack2(b0.x, b0.y), bp01 = pack2(b0.z, b0.w);
        ull bp10 = pack2(b1.x, b1.y), bp11 = pack2(b1.z, b1.w);

#pragma unroll
        for (int r = 0; r < 8; r++) {
            ull ad0 = pack2(a01[r].x, a01[r].x);
            fma2(accp[r][0], ad0, bp00);
            fma2(accp[r][1], ad0, bp01);
            ull ad1 = pack2(a01[r].y, a01[r].y);
            fma2(accp[r][0], ad1, bp10);
            fma2(accp[r][1], ad1, bp11);
        }
    }

    float4 bv = ((const float4*)bvec)[lane];
#pragma unroll
    for (int r = 0; r < 8; r++) {
        int row = row0 + w * 8 + r;
        if (row < n) {
            float2 p0 = unpack2(accp[r][0]);
            float2 p1 = unpack2(accp[r][1]);
            float4 o = make_float4(p0.x + bv.x, p0.y + bv.y, p1.x + bv.z, p1.y + bv.w);
            if (blockIdx.y) {
                ((float4*)g_xr)[row * 32 + lane] = o;
            } else {
                __half2 h01 = __floats2half2_rn(o.x, o.y);
                __half2 h23 = __floats2half2_rn(o.z, o.w);
                uint2 packed;
                packed.x = *(unsigned int*)&h01;
                packed.y = *(unsigned int*)&h23;
                ((uint2*)g_xl16)[row * 32 + lane] = packed;
            }
        }
    }
}

// ---------------- CSR build: count -> 3-step scan -> fill -------------------
__global__ void count_kernel(const int* __restrict__ dst, int E) {
    int base = (blockIdx.x * blockDim.x + threadIdx.x) * 4;
    if (base + 3 < E) {
        int4 d = *(const int4*)(dst + base);
        atomicAdd(&g_cnt[d.x], 1);
        atomicAdd(&g_cnt[d.y], 1);
        atomicAdd(&g_cnt[d.z], 1);
        atomicAdd(&g_cnt[d.w], 1);
    } else {
        for (int i = base; i < E; i++) atomicAdd(&g_cnt[dst[i]], 1);
    }
}

// step 1: per-block sums
__global__ void scan1_kernel(int n) {
    __shared__ int ws[32];
    int idx = blockIdx.x * SCAN_B + threadIdx.x;
    int v = (idx < n) ? g_cnt[idx] : 0;
    int lane = threadIdx.x & 31, wid = threadIdx.x >> 5;
    int s = v;
#pragma unroll
    for (int o = 16; o > 0; o >>= 1) s += __shfl_xor_sync(0xFFFFFFFFu, s, o);
    if (lane == 0) ws[wid] = s;
    __syncthreads();
    if (wid == 0) {
        int t = (lane < SCAN_B / 32) ? ws[lane] : 0;
#pragma unroll
        for (int o = 16; o > 0; o >>= 1) t += __shfl_xor_sync(0xFFFFFFFFu, t, o);
        if (lane == 0) g_bsum[blockIdx.x] = t;
    }
}

// step 2: exclusive scan of <=64 block sums (single small block)
__global__ void scan2_kernel(int nb) {
    __shared__ int s[64];
    int tid = threadIdx.x;
    s[tid] = (tid < nb) ? g_bsum[tid] : 0;
    __syncthreads();
#pragma unroll
    for (int o = 1; o < 64; o <<= 1) {
        int t = (tid >= o) ? s[tid - o] : 0;
        __syncthreads();
        s[tid] += t;
        __syncthreads();
    }
    if (tid < nb) g_boff[tid] = s[tid] - g_bsum[tid];   // exclusive
}

// step 3: block-local exclusive scan + base; emit rowptr, cursor, self-loop
__global__ void scan3_kernel(int n) {
    __shared__ int ws[32];
    int idx = blockIdx.x * SCAN_B + threadIdx.x;
    int v = (idx < n) ? g_cnt[idx] : 0;
    int lane = threadIdx.x & 31, wid = threadIdx.x >> 5;

    int inc = v;
#pragma unroll
    for (int o = 1; o < 32; o <<= 1) {
        int t = __shfl_up_sync(0xFFFFFFFFu, inc, o);
        if (lane >= o) inc += t;
    }
    if (lane == 31) ws[wid] = inc;
    __syncthreads();
    if (wid == 0) {
        int t = (lane < SCAN_B / 32) ? ws[lane] : 0;
#pragma unroll
        for (int o = 1; o < 32; o <<= 1) {
            int u = __shfl_up_sync(0xFFFFFFFFu, t, o);
            if (lane >= o) t += u;
        }
        if (lane < SCAN_B / 32) ws[lane] = t;
    }
    __syncthreads();
    int excl = inc - v + ((wid > 0) ? ws[wid - 1] : 0);
    int base = g_boff[blockIdx.x] + excl;
    if (idx < n) {
        g_rowptr[idx] = base;
        g_src[base] = idx;          // self loop occupies first slot
        g_cursor[idx] = base + 1;
        if (idx == n - 1) g_rowptr[n] = base + v;
    }
}

__global__ void fill_kernel(const int* __restrict__ src, const int* __restrict__ dst,
                            int E) {
    int base = (blockIdx.x * blockDim.x + threadIdx.x) * 4;
    if (base + 3 < E) {
        int4 s = *(const int4*)(src + base);
        int4 d = *(const int4*)(dst + base);
        int p0 = atomicAdd(&g_cursor[d.x], 1);
        int p1 = atomicAdd(&g_cursor[d.y], 1);
        int p2 = atomicAdd(&g_cursor[d.z], 1);
        int p3 = atomicAdd(&g_cursor[d.w], 1);
        g_src[p0] = s.x;
        g_src[p1] = s.y;
        g_src[p2] = s.z;
        g_src[p3] = s.w;
    } else {
        for (int i = base; i < E; i++) {
            int pos = atomicAdd(&g_cursor[dst[i]], 1);
            g_src[pos] = src[i];
        }
    }
}

// ---------------- main fused GATv2 kernel: one warp per dst node ------------
// packed f32x2 math; lrelu(m) = 0.6m + 0.4|m|, attention folded into 0.6a/0.4a
#define ABSMASK 0x7FFFFFFF7FFFFFFFull

__device__ __forceinline__ void ld_xl16p(int j, int lane, ull& x01, ull& x23) {
    uint2 raw = __ldg((const uint2*)g_xl16 + j * 32 + lane);
    float2 f01 = __half22float2(*(__half2*)&raw.x);
    float2 f23 = __half22float2(*(__half2*)&raw.y);
    x01 = pack2(f01.x, f01.y);
    x23 = pack2(f23.x, f23.y);
}

__global__ void gat_main_kernel(const float* __restrict__ att,
                                const float* __restrict__ bias,
                                const int* __restrict__ batch,
                                float* __restrict__ pooled, int n) {
    __shared__ int pbuf[HD];
    __shared__ int bmn, bmx;
    int tid = threadIdx.x;
    if (tid < HD) pbuf[tid] = 0;
    if (tid == 0) { bmn = 1 << 30; bmx = -1; }
    __syncthreads();

    int gw   = (blockIdx.x * blockDim.x + tid) >> 5;
    int lane = tid & 31;
    bool active = (gw < n);
    float4 o = make_float4(0.f, 0.f, 0.f, 0.f);
    int b = 0;

    if (active) {
        int i = gw;
        float4 xrv = ((const float4*)g_xr)[i * 32 + lane];
        float4 av  = ((const float4*)att)[lane];
        ull xr01 = pack2(xrv.x, xrv.y), xr23 = pack2(xrv.z, xrv.w);
        ull a6_01 = pack2(0.6f * av.x, 0.6f * av.y);
        ull a6_23 = pack2(0.6f * av.z, 0.6f * av.w);
        ull a4_01 = pack2(0.4f * av.x, 0.4f * av.y);
        ull a4_23 = pack2(0.4f * av.z, 0.4f * av.w);

        ull acc01 = 0ull, acc23 = 0ull;
        float den = 0.0f;

        int s0 = g_rowptr[i], s1 = g_rowptr[i + 1];
        int k = s0;
        for (; k + 4 <= s1; k += 4) {
            int j[4];
#pragma unroll
            for (int u = 0; u < 4; u++) j[u] = __ldg(&g_src[k + u]);
            ull x01[4], x23[4];
#pragma unroll
            for (int u = 0; u < 4; u++) ld_xl16p(j[u], lane, x01[u], x23[u]);

            float sv[4];
#pragma unroll
            for (int u = 0; u < 4; u++) {
                ull m01 = add2o(x01[u], xr01);
                ull m23 = add2o(x23[u], xr23);
                ull am01 = m01 & ABSMASK;
                ull am23 = m23 & ABSMASK;
                ull s2 = mul2o(a4_23, am23);
                s2 = fma2o(a6_23, m23, s2);
                s2 = fma2o(a4_01, am01, s2);
                s2 = fma2o(a6_01, m01, s2);
                float2 u2 = unpack2(s2);
                sv[u] = u2.x + u2.y;
            }
#pragma unroll
            for (int u = 0; u < 4; u++) {
                sv[u] += __shfl_xor_sync(0xFFFFFFFFu, sv[u], 1);
                sv[u] += __shfl_xor_sync(0xFFFFFFFFu, sv[u], 2);
                sv[u] += __shfl_xor_sync(0xFFFFFFFFu, sv[u], 4);
            }
#pragma unroll
            for (int u = 0; u < 4; u++) {
                float ex = __expf(sv[u]);
                den += ex;
                ull exd = pack2(ex, ex);
                fma2(acc01, exd, x01[u]);
                fma2(acc23, exd, x23[u]);
            }
        }
        for (; k < s1; k++) {
            int j = __ldg(&g_src[k]);
            ull x01, x23;
            ld_xl16p(j, lane, x01, x23);
            ull m01 = add2o(x01, xr01);
            ull m23 = add2o(x23, xr23);
            ull am01 = m01 & ABSMASK;
            ull am23 = m23 & ABSMASK;
            ull s2 = mul2o(a4_23, am23);
            s2 = fma2o(a6_23, m23, s2);
            s2 = fma2o(a4_01, am01, s2);
            s2 = fma2o(a6_01, m01, s2);
            float2 u2 = unpack2(s2);
            float s = u2.x + u2.y;
            s += __shfl_xor_sync(0xFFFFFFFFu, s, 1);
            s += __shfl_xor_sync(0xFFFFFFFFu, s, 2);
            s += __shfl_xor_sync(0xFFFFFFFFu, s, 4);
            float ex = __expf(s);
            den += ex;
            ull exd = pack2(ex, ex);
            fma2(acc01, exd, x01);
            fma2(acc23, exd, x23);
        }

        float inv = 1.0f / den;
        float4 bv = ((const float4*)bias)[lane];
        float2 a01 = unpack2(acc01), a23 = unpack2(acc23);
        o.x = fmaxf(fmaf(a01.x, inv, bv.x), 0.0f);
        o.y = fmaxf(fmaf(a01.y, inv, bv.y), 0.0f);
        o.z = fmaxf(fmaf(a23.x, inv, bv.z), 0.0f);
        o.w = fmaxf(fmaf(a23.y, inv, bv.w), 0.0f);

        b = batch[i];
        if (lane == 0) { atomicMin(&bmn, b); atomicMax(&bmx, b); }
    }
    __syncthreads();

    if (bmn == bmx) {
        if (active) {
            atomicMax(&pbuf[lane * 4 + 0], __float_as_int(o.x));
            atomicMax(&pbuf[lane * 4 + 1], __float_as_int(o.y));
            atomicMax(&pbuf[lane * 4 + 2], __float_as_int(o.z));
            atomicMax(&pbuf[lane * 4 + 3], __float_as_int(o.w));
        }
        __syncthreads();
        if (tid < HD && bmx >= 0)
            atomicMax((int*)pooled + bmx * HD + tid, pbuf[tid]);
    } else if (active) {
        int* pp = (int*)pooled + b * HD + lane * 4;
        atomicMax(pp + 0, __float_as_int(o.x));
        atomicMax(pp + 1, __float_as_int(o.y));
        atomicMax(pp + 2, __float_as_int(o.z));
        atomicMax(pp + 3, __float_as_int(o.w));
    }
}

// ---------------- launcher ---------------------------------------------------
extern "C" void kernel_launch(void* const* d_in, const int* in_sizes, int n_in,
                              void* d_out, int out_size) {
    const float* x    = (const float*)d_in[0];
    const int*   ei   = (const int*)d_in[1];
    const int*   batch= (const int*)d_in[2];
    const float* Wl   = (const float*)d_in[3];
    const float* bl   = (const float*)d_in[4];
    const float* Wr   = (const float*)d_in[5];
    const float* br   = (const float*)d_in[6];
    const float* att  = (const float*)d_in[7];
    const float* bias = (const float*)d_in[8];
    float* out = (float*)d_out;

    int n = in_sizes[2];          // nodes
    int E = in_sizes[1] / 2;      // edges
    const int* esrc = ei;
    const int* edst = ei + E;

    static cudaStream_t s2 = nullptr;
    static cudaEvent_t eFork = nullptr, eJoin = nullptr;
    if (s2 == nullptr) {
        cudaStreamCreateWithFlags(&s2, cudaStreamNonBlocking);
        cudaEventCreateWithFlags(&eFork, cudaEventDisableTiming);
        cudaEventCreateWithFlags(&eJoin, cudaEventDisableTiming);
    }

    int gemm_smem = (64 * HD + HD * HD) * (int)sizeof(float);   // 96 KB
    cudaFuncSetAttribute(gemm_tiled_kernel,
                         cudaFuncAttributeMaxDynamicSharedMemorySize, gemm_smem);

    // fork: CSR build on s2, GEMM on the captured (default) stream
    cudaEventRecord(eFork, 0);
    cudaStreamWaitEvent(s2, eFork, 0);

    int e4 = (E + 3) / 4;
    int nb = (n + SCAN_B - 1) / SCAN_B;
    init_cnt_kernel<<<(n + 255) / 256, 256, 0, s2>>>(n);
    count_kernel<<<(e4 + 255) / 256, 256, 0, s2>>>(edst, E);
    scan1_kernel<<<nb, SCAN_B, 0, s2>>>(n);
    scan2_kernel<<<1, 64, 0, s2>>>(nb);
    scan3_kernel<<<nb, SCAN_B, 0, s2>>>(n);
    fill_kernel<<<(e4 + 255) / 256, 256, 0, s2>>>(esrc, edst, E);
    cudaEventRecord(eJoin, s2);

    init_out_kernel<<<(out_size + 255) / 256, 256>>>(out, out_size);
    dim3 ggrid((n + 63) / 64, 2);
    gemm_tiled_kernel<<<ggrid, 256, gemm_smem>>>(x, Wl, bl, Wr, br, n);

    // join, then fused GATv2 + pool
    cudaStreamWaitEvent(0, eJoin, 0);
    gat_main_kernel<<<(n * 32 + 255) / 256, 256>>>(att, bias, batch, out, n);
}

// round 7
// speedup vs baseline: 1.1018x; 1.1018x over previous
#include <cuda_runtime.h>
#include <cuda_fp16.h>
#include <cuda_bf16.h>

#define NN 50000
#define EE 1600000
#define ETOT (EE + NN)
#define HD 128
#define SCAN_B 1024

typedef unsigned long long ull;

// ---------------- scratch (static device globals; no allocation) ------------
__device__ __half g_xl16[NN * HD];    // fp16 mirror of xl (gathered per edge)
__device__ float  g_xr[NN * HD];
__device__ int    g_cnt[NN];
__device__ int    g_rowptr[NN + 1];
__device__ int    g_cursor[NN];
__device__ int    g_src[ETOT];
__device__ int    g_bsum[64];
__device__ int    g_boff[64];

// ---------------- f32x2 packed-math helpers (GEMM only) ----------------------
__device__ __forceinline__ ull pack2(float lo, float hi) {
    ull r; asm("mov.b64 %0, {%1, %2};" : "=l"(r) : "f"(lo), "f"(hi)); return r;
}
__device__ __forceinline__ float2 unpack2(ull v) {
    float2 r; asm("mov.b64 {%0, %1}, %2;" : "=f"(r.x), "=f"(r.y) : "l"(v)); return r;
}
__device__ __forceinline__ void fma2(ull& d, ull a, ull b) {
    asm("fma.rn.f32x2 %0, %1, %2, %0;" : "+l"(d) : "l"(a), "l"(b));
}

// ---------------- small init kernels ----------------------------------------
__global__ void init_out_kernel(float* __restrict__ out, int out_elems) {
    int i = blockIdx.x * blockDim.x + threadIdx.x;
    if (i < out_elems) out[i] = 0.0f;
}
__global__ void init_cnt_kernel(int n) {
    int i = blockIdx.x * blockDim.x + threadIdx.x;
    if (i < n) g_cnt[i] = 1;                 // self-loop pre-count
}

// ---------------- register-tiled dual GEMM ----------------------------------
__global__ void __launch_bounds__(256, 2)
gemm_tiled_kernel(const float* __restrict__ x,
                  const float* __restrict__ Wl, const float* __restrict__ bl,
                  const float* __restrict__ Wr, const float* __restrict__ br,
                  int n) {
    extern __shared__ float sm[];
    float* xs = sm;                 // [64][128]
    float* ws = sm + 64 * HD;       // [128][128]

    const float* W    = blockIdx.y ? Wr : Wl;
    const float* bvec = blockIdx.y ? br : bl;

    int tid  = threadIdx.x;
    int lane = tid & 31;
    int w    = tid >> 5;
    int row0 = blockIdx.x * 64;

    for (int i4 = tid; i4 < 64 * 32; i4 += 256) {
        int r = i4 >> 5;
        int row = row0 + r;
        float4 v = make_float4(0.f, 0.f, 0.f, 0.f);
        if (row < n) v = ((const float4*)x)[row * 32 + (i4 & 31)];
        ((float4*)xs)[i4] = v;
    }
    for (int i4 = tid; i4 < 128 * 32; i4 += 256)
        ((float4*)ws)[i4] = ((const float4*)W)[i4];
    __syncthreads();

    const float* arow = xs + (w * 8) * HD;
    ull accp[8][2];
#pragma unroll
    for (int r = 0; r < 8; r++) { accp[r][0] = 0ull; accp[r][1] = 0ull; }

#pragma unroll 4
    for (int k = 0; k < HD; k += 2) {
        float2 a01[8];
#pragma unroll
        for (int r = 0; r < 8; r++)
            a01[r] = *(const float2*)(arow + r * HD + k);

        float4 b0 = *(const float4*)(ws + k * HD + 4 * lane);
        float4 b1 = *(const float4*)(ws + (k + 1) * HD + 4 * lane);
        ull bp00 = pack2(b0.x, b0.y), bp01 = pack2(b0.z, b0.w);
        ull bp10 = pack2(b1.x, b1.y), bp11 = pack2(b1.z, b1.w);

#pragma unroll
        for (int r = 0; r < 8; r++) {
            ull ad0 = pack2(a01[r].x, a01[r].x);
            fma2(accp[r][0], ad0, bp00);
            fma2(accp[r][1], ad0, bp01);
            ull ad1 = pack2(a01[r].y, a01[r].y);
            fma2(accp[r][0], ad1, bp10);
            fma2(accp[r][1], ad1, bp11);
        }
    }

    float4 bv = ((const float4*)bvec)[lane];
#pragma unroll
    for (int r = 0; r < 8; r++) {
        int row = row0 + w * 8 + r;
        if (row < n) {
            float2 p0 = unpack2(accp[r][0]);
            float2 p1 = unpack2(accp[r][1]);
            float4 o = make_float4(p0.x + bv.x, p0.y + bv.y, p1.x + bv.z, p1.y + bv.w);
            if (blockIdx.y) {
                ((float4*)g_xr)[row * 32 + lane] = o;
            } else {
                __half2 h01 = __floats2half2_rn(o.x, o.y);
                __half2 h23 = __floats2half2_rn(o.z, o.w);
                uint2 packed;
                packed.x = *(unsigned int*)&h01;
                packed.y = *(unsigned int*)&h23;
                ((uint2*)g_xl16)[row * 32 + lane] = packed;
            }
        }
    }
}

// ---------------- CSR build: count -> 3-step scan -> fill -------------------
__global__ void count_kernel(const int* __restrict__ dst, int E) {
    int base = (blockIdx.x * blockDim.x + threadIdx.x) * 4;
    if (base + 3 < E) {
        int4 d = *(const int4*)(dst + base);
        atomicAdd(&g_cnt[d.x], 1);
        atomicAdd(&g_cnt[d.y], 1);
        atomicAdd(&g_cnt[d.z], 1);
        atomicAdd(&g_cnt[d.w], 1);
    } else {
        for (int i = base; i < E; i++) atomicAdd(&g_cnt[dst[i]], 1);
    }
}

// step 1: per-block sums
__global__ void scan1_kernel(int n) {
    __shared__ int ws[32];
    int idx = blockIdx.x * SCAN_B + threadIdx.x;
    int v = (idx < n) ? g_cnt[idx] : 0;
    int lane = threadIdx.x & 31, wid = threadIdx.x >> 5;
    int s = v;
#pragma unroll
    for (int o = 16; o > 0; o >>= 1) s += __shfl_xor_sync(0xFFFFFFFFu, s, o);
    if (lane == 0) ws[wid] = s;
    __syncthreads();
    if (wid == 0) {
        int t = (lane < SCAN_B / 32) ? ws[lane] : 0;
#pragma unroll
        for (int o = 16; o > 0; o >>= 1) t += __shfl_xor_sync(0xFFFFFFFFu, t, o);
        if (lane == 0) g_bsum[blockIdx.x] = t;
    }
}

// step 2: exclusive scan of <=64 block sums
__global__ void scan2_kernel(int nb) {
    __shared__ int s[64];
    int tid = threadIdx.x;
    s[tid] = (tid < nb) ? g_bsum[tid] : 0;
    __syncthreads();
#pragma unroll
    for (int o = 1; o < 64; o <<= 1) {
        int t = (tid >= o) ? s[tid - o] : 0;
        __syncthreads();
        s[tid] += t;
        __syncthreads();
    }
    if (tid < nb) g_boff[tid] = s[tid] - g_bsum[tid];   // exclusive
}

// step 3: block-local exclusive scan + base; emit rowptr, cursor, self-loop
__global__ void scan3_kernel(int n) {
    __shared__ int ws[32];
    int idx = blockIdx.x * SCAN_B + threadIdx.x;
    int v = (idx < n) ? g_cnt[idx] : 0;
    int lane = threadIdx.x & 31, wid = threadIdx.x >> 5;

    int inc = v;
#pragma unroll
    for (int o = 1; o < 32; o <<= 1) {
        int t = __shfl_up_sync(0xFFFFFFFFu, inc, o);
        if (lane >= o) inc += t;
    }
    if (lane == 31) ws[wid] = inc;
    __syncthreads();
    if (wid == 0) {
        int t = (lane < SCAN_B / 32) ? ws[lane] : 0;
#pragma unroll
        for (int o = 1; o < 32; o <<= 1) {
            int u = __shfl_up_sync(0xFFFFFFFFu, t, o);
            if (lane >= o) t += u;
        }
        if (lane < SCAN_B / 32) ws[lane] = t;
    }
    __syncthreads();
    int excl = inc - v + ((wid > 0) ? ws[wid - 1] : 0);
    int base = g_boff[blockIdx.x] + excl;
    if (idx < n) {
        g_rowptr[idx] = base;
        g_src[base] = idx;          // self loop occupies first slot
        g_cursor[idx] = base + 1;
        if (idx == n - 1) g_rowptr[n] = base + v;
    }
}

__global__ void fill_kernel(const int* __restrict__ src, const int* __restrict__ dst,
                            int E) {
    int base = (blockIdx.x * blockDim.x + threadIdx.x) * 4;
    if (base + 3 < E) {
        int4 s = *(const int4*)(src + base);
        int4 d = *(const int4*)(dst + base);
        int p0 = atomicAdd(&g_cursor[d.x], 1);
        int p1 = atomicAdd(&g_cursor[d.y], 1);
        int p2 = atomicAdd(&g_cursor[d.z], 1);
        int p3 = atomicAdd(&g_cursor[d.w], 1);
        g_src[p0] = s.x;
        g_src[p1] = s.y;
        g_src[p2] = s.z;
        g_src[p3] = s.w;
    } else {
        for (int i = base; i < E; i++) {
            int pos = atomicAdd(&g_cursor[dst[i]], 1);
            g_src[pos] = src[i];
        }
    }
}

// ---------------- main fused GATv2 kernel: one warp per dst node ------------
// scalar math; lrelu(m)*a = (0.6a)*m + (0.4a)*|m| (FABS folds into FFMA operand)
// logit sum built as 2 independent trees; dual accumulators break the
// loop-carried recurrence across the 4-edge unroll.
__device__ __forceinline__ float4 ld_xl16(int j, int lane) {
    uint2 raw = __ldg((const uint2*)g_xl16 + j * 32 + lane);
    float2 f01 = __half22float2(*(__half2*)&raw.x);
    float2 f23 = __half22float2(*(__half2*)&raw.y);
    return make_float4(f01.x, f01.y, f23.x, f23.y);
}
__device__ __forceinline__ float hsum8(float s) {
    s += __shfl_xor_sync(0xFFFFFFFFu, s, 1);
    s += __shfl_xor_sync(0xFFFFFFFFu, s, 2);
    s += __shfl_xor_sync(0xFFFFFFFFu, s, 4);
    return s;
}

__global__ void __launch_bounds__(256)
gat_main_kernel(const float* __restrict__ att,
                const float* __restrict__ bias,
                const int* __restrict__ batch,
                float* __restrict__ pooled, int n) {
    __shared__ int pbuf[HD];
    __shared__ int bmn, bmx;
    int tid = threadIdx.x;
    if (tid < HD) pbuf[tid] = 0;
    if (tid == 0) { bmn = 1 << 30; bmx = -1; }
    __syncthreads();

    int gw   = (blockIdx.x * blockDim.x + tid) >> 5;
    int lane = tid & 31;
    bool active = (gw < n);
    float4 o = make_float4(0.f, 0.f, 0.f, 0.f);
    int b = 0;

    if (active) {
        int i = gw;
        float4 xr = ((const float4*)g_xr)[i * 32 + lane];
        float4 av = ((const float4*)att)[lane];
        float4 a6 = make_float4(0.6f * av.x, 0.6f * av.y, 0.6f * av.z, 0.6f * av.w);
        float4 a4 = make_float4(0.4f * av.x, 0.4f * av.y, 0.4f * av.z, 0.4f * av.w);

        float4 acc0 = make_float4(0.f, 0.f, 0.f, 0.f);
        float4 acc1 = make_float4(0.f, 0.f, 0.f, 0.f);
        float den0 = 0.0f, den1 = 0.0f;

        int s0 = g_rowptr[i], s1 = g_rowptr[i + 1];
        int k = s0;
        for (; k + 4 <= s1; k += 4) {       // 4 independent gathers in flight
            int j[4];
#pragma unroll
            for (int u = 0; u < 4; u++) j[u] = __ldg(&g_src[k + u]);
            float4 xv[4];
#pragma unroll
            for (int u = 0; u < 4; u++) xv[u] = ld_xl16(j[u], lane);

            float s[4];
#pragma unroll
            for (int u = 0; u < 4; u++) {
                float mx = xv[u].x + xr.x, my = xv[u].y + xr.y;
                float mz = xv[u].z + xr.z, mw = xv[u].w + xr.w;
                // two independent 4-deep trees
                float t0 = a6.x * mx;
                t0 = fmaf(a4.x, fabsf(mx), t0);
                t0 = fmaf(a6.y, my, t0);
                t0 = fmaf(a4.y, fabsf(my), t0);
                float t1 = a6.z * mz;
                t1 = fmaf(a4.z, fabsf(mz), t1);
                t1 = fmaf(a6.w, mw, t1);
                t1 = fmaf(a4.w, fabsf(mw), t1);
                s[u] = t0 + t1;
            }
#pragma unroll
            for (int u = 0; u < 4; u++) s[u] = hsum8(s[u]);

            float e0 = __expf(s[0]), e1 = __expf(s[1]);
            float e2 = __expf(s[2]), e3 = __expf(s[3]);
            den0 += e0 + e2;
            den1 += e1 + e3;
            acc0.x = fmaf(e0, xv[0].x, acc0.x); acc1.x = fmaf(e1, xv[1].x, acc1.x);
            acc0.y = fmaf(e0, xv[0].y, acc0.y); acc1.y = fmaf(e1, xv[1].y, acc1.y);
            acc0.z = fmaf(e0, xv[0].z, acc0.z); acc1.z = fmaf(e1, xv[1].z, acc1.z);
            acc0.w = fmaf(e0, xv[0].w, acc0.w); acc1.w = fmaf(e1, xv[1].w, acc1.w);
            acc0.x = fmaf(e2, xv[2].x, acc0.x); acc1.x = fmaf(e3, xv[3].x, acc1.x);
            acc0.y = fmaf(e2, xv[2].y, acc0.y); acc1.y = fmaf(e3, xv[3].y, acc1.y);
            acc0.z = fmaf(e2, xv[2].z, acc0.z); acc1.z = fmaf(e3, xv[3].z, acc1.z);
            acc0.w = fmaf(e2, xv[2].w, acc0.w); acc1.w = fmaf(e3, xv[3].w, acc1.w);
        }
        for (; k < s1; k++) {
            int j = __ldg(&g_src[k]);
            float4 xl = ld_xl16(j, lane);
            float mx = xl.x + xr.x, my = xl.y + xr.y;
            float mz = xl.z + xr.z, mw = xl.w + xr.w;
            float t0 = a6.x * mx;
            t0 = fmaf(a4.x, fabsf(mx), t0);
            t0 = fmaf(a6.y, my, t0);
            t0 = fmaf(a4.y, fabsf(my), t0);
            float t1 = a6.z * mz;
            t1 = fmaf(a4.z, fabsf(mz), t1);
            t1 = fmaf(a6.w, mw, t1);
            t1 = fmaf(a4.w, fabsf(mw), t1);
            float s = hsum8(t0 + t1);
            float ex = __expf(s);
            den0 += ex;
            acc0.x = fmaf(ex, xl.x, acc0.x);
            acc0.y = fmaf(ex, xl.y, acc0.y);
            acc0.z = fmaf(ex, xl.z, acc0.z);
            acc0.w = fmaf(ex, xl.w, acc0.w);
        }

        float inv = 1.0f / (den0 + den1);
        float4 bv = ((const float4*)bias)[lane];
        o.x = fmaxf(fmaf(acc0.x + acc1.x, inv, bv.x), 0.0f);
        o.y = fmaxf(fmaf(acc0.y + acc1.y, inv, bv.y), 0.0f);
        o.z = fmaxf(fmaf(acc0.z + acc1.z, inv, bv.z), 0.0f);
        o.w = fmaxf(fmaf(acc0.w + acc1.w, inv, bv.w), 0.0f);

        b = batch[i];
        if (lane == 0) { atomicMin(&bmn, b); atomicMax(&bmx, b); }
    }
    __syncthreads();

    if (bmn == bmx) {
        if (active) {
            atomicMax(&pbuf[lane * 4 + 0], __float_as_int(o.x));
            atomicMax(&pbuf[lane * 4 + 1], __float_as_int(o.y));
            atomicMax(&pbuf[lane * 4 + 2], __float_as_int(o.z));
            atomicMax(&pbuf[lane * 4 + 3], __float_as_int(o.w));
        }
        __syncthreads();
        if (tid < HD && bmx >= 0)
            atomicMax((int*)pooled + bmx * HD + tid, pbuf[tid]);
    } else if (active) {
        int* pp = (int*)pooled + b * HD + lane * 4;
        atomicMax(pp + 0, __float_as_int(o.x));
        atomicMax(pp + 1, __float_as_int(o.y));
        atomicMax(pp + 2, __float_as_int(o.z));
        atomicMax(pp + 3, __float_as_int(o.w));
    }
}

// ---------------- launcher ---------------------------------------------------
extern "C" void kernel_launch(void* const* d_in, const int* in_sizes, int n_in,
                              void* d_out, int out_size) {
    const float* x    = (const float*)d_in[0];
    const int*   ei   = (const int*)d_in[1];
    const int*   batch= (const int*)d_in[2];
    const float* Wl   = (const float*)d_in[3];
    const float* bl   = (const float*)d_in[4];
    const float* Wr   = (const float*)d_in[5];
    const float* br   = (const float*)d_in[6];
    const float* att  = (const float*)d_in[7];
    const float* bias = (const float*)d_in[8];
    float* out = (float*)d_out;

    int n = in_sizes[2];          // nodes
    int E = in_sizes[1] / 2;      // edges
    const int* esrc = ei;
    const int* edst = ei + E;

    static cudaStream_t s2 = nullptr;
    static cudaEvent_t eFork = nullptr, eJoin = nullptr;
    if (s2 == nullptr) {
        cudaStreamCreateWithFlags(&s2, cudaStreamNonBlocking);
        cudaEventCreateWithFlags(&eFork, cudaEventDisableTiming);
        cudaEventCreateWithFlags(&eJoin, cudaEventDisableTiming);
    }

    int gemm_smem = (64 * HD + HD * HD) * (int)sizeof(float);   // 96 KB
    cudaFuncSetAttribute(gemm_tiled_kernel,
                         cudaFuncAttributeMaxDynamicSharedMemorySize, gemm_smem);

    // fork: CSR build on s2, GEMM on the captured (default) stream
    cudaEventRecord(eFork, 0);
    cudaStreamWaitEvent(s2, eFork, 0);

    int e4 = (E + 3) / 4;
    int nb = (n + SCAN_B - 1) / SCAN_B;
    init_cnt_kernel<<<(n + 255) / 256, 256, 0, s2>>>(n);
    count_kernel<<<(e4 + 255) / 256, 256, 0, s2>>>(edst, E);
    scan1_kernel<<<nb, SCAN_B, 0, s2>>>(n);
    scan2_kernel<<<1, 64, 0, s2>>>(nb);
    scan3_kernel<<<nb, SCAN_B, 0, s2>>>(n);
    fill_kernel<<<(e4 + 255) / 256, 256, 0, s2>>>(esrc, edst, E);
    cudaEventRecord(eJoin, s2);

    init_out_kernel<<<(out_size + 255) / 256, 256>>>(out, out_size);
    dim3 ggrid((n + 63) / 64, 2);
    gemm_tiled_kernel<<<ggrid, 256, gemm_smem>>>(x, Wl, bl, Wr, br, n);

    // join, then fused GATv2 + pool
    cudaStreamWaitEvent(0, eJoin, 0);
    gat_main_kernel<<<(n * 32 + 255) / 256, 256>>>(att, bias, batch, out, n);
}